// round 3
// baseline (speedup 1.0000x reference)
#include <cuda_runtime.h>
#include <math.h>

#define BATCH 32
#define H 512
#define W 512
#define NPIX (H*W)
#define EPSF 1e-4f
#define RSTRIP 16
#define NTHR 256

// ---------------- scratch (device globals; no allocation allowed) -------------
__device__ float g_hist[BATCH * 256];
__device__ float g_ls1[BATCH];   // sum of laplacian
__device__ float g_ls2[BATCH];   // sum of laplacian^2
__device__ float g_dn[BATCH];    // depth mask count
__device__ float g_ds1[BATCH];   // sum depth*mask
__device__ float g_ds2[BATCH];   // sum depth^2*mask

// ---------------- zero accumulators -------------------------------------------
__global__ void zero_kernel() {
    int i = blockIdx.x * blockDim.x + threadIdx.x;
    if (i < BATCH * 256) g_hist[i] = 0.0f;
    if (i < BATCH) {
        g_ls1[i] = 0.0f; g_ls2[i] = 0.0f;
        g_dn[i] = 0.0f;  g_ds1[i] = 0.0f; g_ds2[i] = 0.0f;
    }
}

// ---------------- block reduce helper ------------------------------------------
__device__ __forceinline__ float warp_sum(float v) {
    #pragma unroll
    for (int o = 16; o > 0; o >>= 1) v += __shfl_down_sync(0xffffffffu, v, o);
    return v;
}

// ---------------- RGB kernel: gray -> laplacian sums + histogram ---------------
// grid: (H/RSTRIP, BATCH), block: 256 threads
__global__ __launch_bounds__(NTHR) void rgb_kernel(const float* __restrict__ rgb) {
    __shared__ float tile[(RSTRIP + 2) * W];   // gray strip with 1-row halo
    __shared__ int   shist[256];
    __shared__ float sred[16];

    const int b   = blockIdx.y;
    const int rs  = blockIdx.x * RSTRIP;
    const int tid = threadIdx.x;

    shist[tid] = 0;

    const float* base = rgb + (size_t)b * 3 * NPIX;

    // Load gray tile (vectorized float4). Rows outside image -> 0 (zero padding).
    const int W4 = W / 4;
    for (int v = tid; v < (RSTRIP + 2) * W4; v += NTHR) {
        int row = v / W4;
        int c4  = v - row * W4;
        int gr  = rs - 1 + row;
        float4 gout;
        if (gr >= 0 && gr < H) {
            const float4* rp = (const float4*)(base + (size_t)gr * W);
            const float4* gp = (const float4*)(base + NPIX + (size_t)gr * W);
            const float4* bp = (const float4*)(base + 2 * NPIX + (size_t)gr * W);
            float4 r = __ldg(rp + c4);
            float4 g = __ldg(gp + c4);
            float4 bl = __ldg(bp + c4);
            gout.x = 0.299f * r.x + 0.587f * g.x + 0.114f * bl.x;
            gout.y = 0.299f * r.y + 0.587f * g.y + 0.114f * bl.y;
            gout.z = 0.299f * r.z + 0.587f * g.z + 0.114f * bl.z;
            gout.w = 0.299f * r.w + 0.587f * g.w + 0.114f * bl.w;
        } else {
            gout.x = gout.y = gout.z = gout.w = 0.0f;
        }
        ((float4*)tile)[row * W4 + c4] = gout;
    }
    __syncthreads();

    // Laplacian + histogram over interior rows [rs, rs+RSTRIP)
    float s1 = 0.0f, s2 = 0.0f;
    #pragma unroll
    for (int p = 0; p < (RSTRIP * W) / NTHR; p++) {
        int idx = tid + p * NTHR;
        int r = idx >> 9;          // /512
        int c = idx & (W - 1);     // %512
        const float* trow = tile + (r + 1) * W;
        float gc = trow[c];
        float lap = tile[r * W + c] + tile[(r + 2) * W + c] - 4.0f * gc;
        if (c > 0)     lap += trow[c - 1];
        if (c < W - 1) lap += trow[c + 1];
        s1 += lap;
        s2 += lap * lap;
        int bin = (int)fminf(fmaxf(gc * 255.0f, 0.0f), 255.0f);
        atomicAdd(&shist[bin], 1);
    }

    // Reduce s1, s2 across the block
    s1 = warp_sum(s1);
    s2 = warp_sum(s2);
    int lane = tid & 31, w = tid >> 5;
    if (lane == 0) { sred[w] = s1; sred[8 + w] = s2; }
    __syncthreads();
    if (w == 0) {
        float v1 = (lane < 8) ? sred[lane] : 0.0f;
        float v2 = (lane < 8) ? sred[8 + lane] : 0.0f;
        v1 = warp_sum(v1);
        v2 = warp_sum(v2);
        if (lane == 0) {
            atomicAdd(&g_ls1[b], v1);
            atomicAdd(&g_ls2[b], v2);
        }
    }

    // Flush histogram (shist final after the __syncthreads above)
    int hc = shist[tid];
    if (hc != 0) atomicAdd(&g_hist[b * 256 + tid], (float)hc);
}

// ---------------- depth kernel: masked sums ------------------------------------
// grid: (16, BATCH), block: 256 threads
__global__ __launch_bounds__(NTHR) void depth_kernel(const float* __restrict__ depth) {
    __shared__ float sred[24];
    const int b = blockIdx.y;
    const float4* d4 = (const float4*)(depth + (size_t)b * NPIX);
    const int nvec = NPIX / 4;

    float n = 0.0f, s1 = 0.0f, s2 = 0.0f;
    for (int i = blockIdx.x * NTHR + threadIdx.x; i < nvec; i += gridDim.x * NTHR) {
        float4 v = __ldg(d4 + i);
        if (v.x > 0.0f) { n += 1.0f; s1 += v.x; s2 += v.x * v.x; }
        if (v.y > 0.0f) { n += 1.0f; s1 += v.y; s2 += v.y * v.y; }
        if (v.z > 0.0f) { n += 1.0f; s1 += v.z; s2 += v.z * v.z; }
        if (v.w > 0.0f) { n += 1.0f; s1 += v.w; s2 += v.w * v.w; }
    }

    n  = warp_sum(n);
    s1 = warp_sum(s1);
    s2 = warp_sum(s2);
    int lane = threadIdx.x & 31, w = threadIdx.x >> 5;
    if (lane == 0) { sred[w] = n; sred[8 + w] = s1; sred[16 + w] = s2; }
    __syncthreads();
    if (w == 0) {
        float vn = (lane < 8) ? sred[lane] : 0.0f;
        float v1 = (lane < 8) ? sred[8 + lane] : 0.0f;
        float v2 = (lane < 8) ? sred[16 + lane] : 0.0f;
        vn = warp_sum(vn);
        v1 = warp_sum(v1);
        v2 = warp_sum(v2);
        if (lane == 0) {
            atomicAdd(&g_dn[b], vn);
            atomicAdd(&g_ds1[b], v1);
            atomicAdd(&g_ds2[b], v2);
        }
    }
}

// ---------------- finalize: entropy, scores, weights ---------------------------
// grid: BATCH blocks, 256 threads (one thread per histogram bin)
__global__ __launch_bounds__(NTHR) void final_kernel(float* __restrict__ out) {
    __shared__ float sred[8];
    const int b = blockIdx.x;
    const int t = threadIdx.x;

    float cnt = g_hist[b * 256 + t];
    float p = cnt * (1.0f / (float)NPIX);
    float e = -p * log2f(p + EPSF);

    e = warp_sum(e);
    int lane = t & 31, w = t >> 5;
    if (lane == 0) sred[w] = e;
    __syncthreads();
    if (t == 0) {
        float entropy = 0.0f;
        #pragma unroll
        for (int i = 0; i < 8; i++) entropy += sred[i];

        const float N = (float)NPIX;
        // laplace variance, ddof=1
        float s1 = g_ls1[b], s2 = g_ls2[b];
        float lvar = (s2 - s1 * s1 / N) / (N - 1.0f);
        float clarity = lvar / (1000.0f + EPSF);
        float uniformity = 1.0f / (entropy + EPSF);
        float rgb_conf = 0.5f * (clarity + uniformity);

        // depth
        float dn = g_dn[b], ds1 = g_ds1[b], ds2 = g_ds2[b];
        float density = dn / N;
        float mean = ds1 / fmaxf(dn, 1.0f);
        float sq = ds2 - 2.0f * mean * ds1 + mean * mean * dn;
        float dvar = sq / fmaxf(dn - 1.0f, 1.0f);
        float dstd = sqrtf(fmaxf(dvar, 0.0f));
        float noise = (dn > 0.0f) ? dstd : 1.0f;
        float density_score = density / (10000.0f + EPSF);
        float noise_score = 1.0f / (noise + EPSF);
        float depth_conf = 0.5f * (density_score + noise_score);

        float denom = rgb_conf + depth_conf + EPSF;
        out[b]         = rgb_conf / denom;   // w_r
        out[BATCH + b] = depth_conf / denom; // w_d
    }
}

// ---------------- launch -------------------------------------------------------
extern "C" void kernel_launch(void* const* d_in, const int* in_sizes, int n_in,
                              void* d_out, int out_size) {
    const float* rgb   = (const float*)d_in[0];
    const float* depth = (const float*)d_in[1];
    float* out = (float*)d_out;

    zero_kernel<<<(BATCH * 256 + NTHR - 1) / NTHR, NTHR>>>();
    {
        dim3 grid(H / RSTRIP, BATCH);
        rgb_kernel<<<grid, NTHR>>>(rgb);
    }
    {
        dim3 grid(16, BATCH);
        depth_kernel<<<grid, NTHR>>>(depth);
    }
    final_kernel<<<BATCH, NTHR>>>(out);
}

// round 9
// speedup vs baseline: 1.1813x; 1.1813x over previous
#include <cuda_runtime.h>
#include <math.h>

#define BATCH 32
#define H 512
#define W 512
#define NPIX (H*W)
#define EPSF 1e-4f
#define RSTRIP 16
#define NTHR 256

#define RGB_BLKS 32            // strips per batch = H / RSTRIP = 512/16 = 32
#define DEP_BLKS 16            // depth slices per batch

// ---------------- per-block partial outputs (device globals) -------------------
// STATELESS DESIGN: every slot below is unconditionally overwritten by
// accum_kernel on every invocation before final_kernel reads it. No zeroing,
// no resets, no atomics, nothing carried between kernel_launch calls.
__device__ int   g_hist_part[BATCH][RGB_BLKS][256];   // per-strip histograms
__device__ float g_lap_part [BATCH][RGB_BLKS][2];     // per-strip (sum, sumsq)
__device__ float g_dep_part [BATCH][DEP_BLKS][3];     // per-slice (n, sum, sumsq)

__device__ __forceinline__ float warp_sum(float v) {
    #pragma unroll
    for (int o = 16; o > 0; o >>= 1) v += __shfl_down_sync(0xffffffffu, v, o);
    return v;
}

// ---------------- fused accumulate kernel -------------------------------------
// grid: (RGB_BLKS + DEP_BLKS, BATCH), block: 256
//   blockIdx.x <  RGB_BLKS : rgb strip blockIdx.x of batch blockIdx.y
//   blockIdx.x >= RGB_BLKS : depth slice (blockIdx.x - RGB_BLKS) of batch
__global__ __launch_bounds__(NTHR) void accum_kernel(
    const float* __restrict__ rgb,
    const float* __restrict__ depth)
{
    __shared__ float tile[(RSTRIP + 2) * W];   // gray strip + 1-row halo (36 KB)
    __shared__ int   shist[256];
    __shared__ float sred[24];

    const int b   = blockIdx.y;
    const int bx  = blockIdx.x;
    const int tid = threadIdx.x;
    const int lane = tid & 31, w = tid >> 5;

    if (bx < RGB_BLKS) {
        // ================= RGB: gray -> laplacian partials + strip histogram ==
        const int rs = bx * RSTRIP;
        shist[tid] = 0;

        const float* base = rgb + (size_t)b * 3 * NPIX;
        const int W4 = W / 4;
        for (int v = tid; v < (RSTRIP + 2) * W4; v += NTHR) {
            int row = v / W4;
            int c4  = v - row * W4;
            int gr  = rs - 1 + row;
            float4 gout;
            if (gr >= 0 && gr < H) {
                const float4* rp = (const float4*)(base + (size_t)gr * W);
                const float4* gp = (const float4*)(base + NPIX + (size_t)gr * W);
                const float4* bp = (const float4*)(base + 2 * NPIX + (size_t)gr * W);
                float4 r  = __ldg(rp + c4);
                float4 g  = __ldg(gp + c4);
                float4 bl = __ldg(bp + c4);
                gout.x = 0.299f * r.x + 0.587f * g.x + 0.114f * bl.x;
                gout.y = 0.299f * r.y + 0.587f * g.y + 0.114f * bl.y;
                gout.z = 0.299f * r.z + 0.587f * g.z + 0.114f * bl.z;
                gout.w = 0.299f * r.w + 0.587f * g.w + 0.114f * bl.w;
            } else {
                gout.x = gout.y = gout.z = gout.w = 0.0f;
            }
            ((float4*)tile)[row * W4 + c4] = gout;
        }
        __syncthreads();

        float s1 = 0.0f, s2 = 0.0f;
        #pragma unroll
        for (int p = 0; p < (RSTRIP * W) / NTHR; p++) {
            int idx = tid + p * NTHR;
            int r = idx >> 9;
            int c = idx & (W - 1);
            const float* trow = tile + (r + 1) * W;
            float gc = trow[c];
            float lap = tile[r * W + c] + tile[(r + 2) * W + c] - 4.0f * gc;
            if (c > 0)     lap += trow[c - 1];
            if (c < W - 1) lap += trow[c + 1];
            s1 += lap;
            s2 += lap * lap;
            int bin = (int)fminf(fmaxf(gc * 255.0f, 0.0f), 255.0f);
            atomicAdd(&shist[bin], 1);   // block-local smem atomic only
        }

        s1 = warp_sum(s1);
        s2 = warp_sum(s2);
        if (lane == 0) { sred[w] = s1; sred[8 + w] = s2; }
        __syncthreads();
        if (w == 0) {
            float v1 = (lane < 8) ? sred[lane] : 0.0f;
            float v2 = (lane < 8) ? sred[8 + lane] : 0.0f;
            v1 = warp_sum(v1);
            v2 = warp_sum(v2);
            if (lane == 0) {
                g_lap_part[b][bx][0] = v1;   // plain store to private slot
                g_lap_part[b][bx][1] = v2;
            }
        }
        // strip histogram: plain store to this block's private slot
        // (shist is final: last atomicAdd precedes the __syncthreads above)
        g_hist_part[b][bx][tid] = shist[tid];
    } else {
        // ================= depth: masked partial sums =========================
        const int part = bx - RGB_BLKS;
        const float4* d4 = (const float4*)(depth + (size_t)b * NPIX);
        const int per = (NPIX / 4) / DEP_BLKS;   // 4096 float4 per slice

        float n = 0.0f, s1 = 0.0f, s2 = 0.0f;
        #pragma unroll 4
        for (int k = 0; k < per / NTHR; k++) {
            float4 v = __ldg(d4 + part * per + k * NTHR + tid);
            if (v.x > 0.0f) { n += 1.0f; s1 += v.x; s2 += v.x * v.x; }
            if (v.y > 0.0f) { n += 1.0f; s1 += v.y; s2 += v.y * v.y; }
            if (v.z > 0.0f) { n += 1.0f; s1 += v.z; s2 += v.z * v.z; }
            if (v.w > 0.0f) { n += 1.0f; s1 += v.w; s2 += v.w * v.w; }
        }
        n  = warp_sum(n);
        s1 = warp_sum(s1);
        s2 = warp_sum(s2);
        if (lane == 0) { sred[w] = n; sred[8 + w] = s1; sred[16 + w] = s2; }
        __syncthreads();
        if (w == 0) {
            float vn = (lane < 8) ? sred[lane] : 0.0f;
            float v1 = (lane < 8) ? sred[8 + lane] : 0.0f;
            float v2 = (lane < 8) ? sred[16 + lane] : 0.0f;
            vn = warp_sum(vn);
            v1 = warp_sum(v1);
            v2 = warp_sum(v2);
            if (lane == 0) {
                g_dep_part[b][part][0] = vn;   // plain store to private slot
                g_dep_part[b][part][1] = v1;
                g_dep_part[b][part][2] = v2;
            }
        }
    }
}

// ---------------- finalize kernel ----------------------------------------------
// grid: BATCH blocks, 256 threads. Pure function of the partials written by
// accum_kernel in this same invocation — reads everything, carries nothing.
__global__ __launch_bounds__(NTHR) void final_kernel(float* __restrict__ out) {
    __shared__ float sred[8];
    const int b = blockIdx.x;
    const int t = threadIdx.x;

    // sum the 32 strip histograms for bin t (coalesced across threads)
    int cnt = 0;
    #pragma unroll
    for (int s = 0; s < RGB_BLKS; s++) cnt += g_hist_part[b][s][t];
    float p = (float)cnt * (1.0f / (float)NPIX);
    float e = -p * log2f(p + EPSF);

    e = warp_sum(e);
    int lane = t & 31, w = t >> 5;
    if (lane == 0) sred[w] = e;
    __syncthreads();
    if (t == 0) {
        float entropy = 0.0f;
        #pragma unroll
        for (int i = 0; i < 8; i++) entropy += sred[i];

        // reduce laplace + depth partials (independent loads, MLP-covered)
        float s1 = 0.0f, s2 = 0.0f, dn = 0.0f, ds1 = 0.0f, ds2 = 0.0f;
        #pragma unroll
        for (int s = 0; s < RGB_BLKS; s++) {
            s1 += g_lap_part[b][s][0];
            s2 += g_lap_part[b][s][1];
        }
        #pragma unroll
        for (int s = 0; s < DEP_BLKS; s++) {
            dn  += g_dep_part[b][s][0];
            ds1 += g_dep_part[b][s][1];
            ds2 += g_dep_part[b][s][2];
        }

        const float N = (float)NPIX;
        float lvar = (s2 - s1 * s1 / N) / (N - 1.0f);
        float clarity = lvar / (1000.0f + EPSF);
        float uniformity = 1.0f / (entropy + EPSF);
        float rgb_conf = 0.5f * (clarity + uniformity);

        float density = dn / N;
        float mean = ds1 / fmaxf(dn, 1.0f);
        float sq = ds2 - 2.0f * mean * ds1 + mean * mean * dn;
        float dvar = sq / fmaxf(dn - 1.0f, 1.0f);
        float dstd = sqrtf(fmaxf(dvar, 0.0f));
        float noise = (dn > 0.0f) ? dstd : 1.0f;
        float density_score = density / (10000.0f + EPSF);
        float noise_score = 1.0f / (noise + EPSF);
        float depth_conf = 0.5f * (density_score + noise_score);

        float denom = rgb_conf + depth_conf + EPSF;
        out[b]         = rgb_conf / denom;    // w_r
        out[BATCH + b] = depth_conf / denom;  // w_d
    }
}

// ---------------- launch -------------------------------------------------------
extern "C" void kernel_launch(void* const* d_in, const int* in_sizes, int n_in,
                              void* d_out, int out_size) {
    const float* rgb   = (const float*)d_in[0];
    const float* depth = (const float*)d_in[1];
    float* out = (float*)d_out;

    dim3 grid(RGB_BLKS + DEP_BLKS, BATCH);
    accum_kernel<<<grid, NTHR>>>(rgb, depth);
    final_kernel<<<BATCH, NTHR>>>(out);
}